// round 10
// baseline (speedup 1.0000x reference)
#include <cuda_runtime.h>
#include <cstdint>

// Batched OSQP ADMM: B=64, n=256, m=512, 200 iterations.
// setup1: syrk  M = rho*A'A + diag(P)+sigma
// setup2: Cholesky (1024 thr, 4-way k-split) + conflict-free L -> g_W
// minv:   2 blocks/batch x 1024 thr, blocked identity solves -> g_Minv
// admm:   2-CTA cluster per batch (grid 128), 1024 thr/CTA, 100 iters/launch.
//         Each rank owns constraints m in [r*256, r*256+256): A rows cached in
//         SMEM (192 of 256, XOR-swizzled) serve BOTH A^T w and A x~ (no At).
//         Minv output-split. 2 DSMEM exchanges + 2 cluster barriers per iter.

#define NBAT 64
#define NV   256
#define MCON 512

__device__ float g_M   [(size_t)NBAT*NV*NV];    // M, then L (col-major lower)
__device__ float g_W   [(size_t)NBAT*NV*NV];    // L row-major
__device__ float g_Minv[(size_t)NBAT*NV*NV];    // M^{-1}, row-major
__device__ float g_state[(size_t)NBAT*1280];    // x 256 | z 512 | y 512

__device__ __forceinline__ void fma4(float4& a, const float4 v, const float s) {
    a.x = fmaf(v.x, s, a.x); a.y = fmaf(v.y, s, a.y);
    a.z = fmaf(v.z, s, a.z); a.w = fmaf(v.w, s, a.w);
}
__device__ __forceinline__ void dot4(float4& a, const float4 v, const float4 s) {
    a.x = fmaf(v.x, s.x, a.x); a.y = fmaf(v.y, s.y, a.y);
    a.z = fmaf(v.z, s.z, a.z); a.w = fmaf(v.w, s.w, a.w);
}
__device__ __forceinline__ uint32_t mapa_u32(uint32_t laddr, uint32_t rank) {
    uint32_t ra;
    asm("mapa.shared::cluster.u32 %0, %1, %2;" : "=r"(ra) : "r"(laddr), "r"(rank));
    return ra;
}
__device__ __forceinline__ void st_cluster_f32(uint32_t addr, float v) {
    asm volatile("st.shared::cluster.f32 [%0], %1;" :: "r"(addr), "f"(v) : "memory");
}
#define CLUSTER_ARRIVE() asm volatile("barrier.cluster.arrive.aligned;" ::: "memory")
#define CLUSTER_WAIT()   asm volatile("barrier.cluster.wait.aligned;"   ::: "memory")

// ---------------------------------------------------------------------------
// setup1: syrk 64x64 tile pairs, 10 blocks per batch.
// ---------------------------------------------------------------------------
__global__ void __launch_bounds__(256) setup1_kernel(const float* __restrict__ A,
                                                     const float* __restrict__ P)
{
    const int pr = blockIdx.x, b = blockIdx.y;
    const int tid = threadIdx.x;
    int ti, tj;
    if      (pr < 4) { ti = 0; tj = pr;     }
    else if (pr < 7) { ti = 1; tj = pr - 3; }
    else if (pr < 9) { ti = 2; tj = pr - 5; }
    else             { ti = 3; tj = 3;      }

    __shared__ float As[16 * 64], Bs[16 * 64];
    const float* Ab = A + (size_t)b * MCON * NV;
    const int lr = tid >> 4, lc = tid & 15;

    float acc[4][4] = {};
    for (int k0 = 0; k0 < MCON; k0 += 16) {
        *(float4*)(As + lr*64 + lc*4) = *(const float4*)(Ab + (size_t)(k0+lr)*NV + ti*64 + lc*4);
        *(float4*)(Bs + lr*64 + lc*4) = *(const float4*)(Ab + (size_t)(k0+lr)*NV + tj*64 + lc*4);
        __syncthreads();
#pragma unroll
        for (int kk = 0; kk < 16; kk++) {
            float4 a4 = *(float4*)(As + kk*64 + lr*4);
            float4 b4 = *(float4*)(Bs + kk*64 + lc*4);
            float av[4] = {a4.x, a4.y, a4.z, a4.w};
            float bv[4] = {b4.x, b4.y, b4.z, b4.w};
#pragma unroll
            for (int r = 0; r < 4; r++)
#pragma unroll
                for (int s = 0; s < 4; s++)
                    acc[r][s] = fmaf(av[r], bv[s], acc[r][s]);
        }
        __syncthreads();
    }

    float* Mb = g_M + (size_t)b * NV * NV;
    const float RHO = 0.1f, SIGMA = 1e-6f;
#pragma unroll
    for (int r = 0; r < 4; r++)
#pragma unroll
        for (int s = 0; s < 4; s++) {
            int i = ti*64 + lr*4 + r;
            int j = tj*64 + lc*4 + s;
            float v = RHO * acc[r][s];
            if (i == j) v += P[b*NV + i] + SIGMA;
            Mb[(size_t)i*NV + j] = v;
            if (ti != tj) Mb[(size_t)j*NV + i] = v;
        }
}

// ---------------------------------------------------------------------------
// setup2: Cholesky, 1024 threads, 4-way k-split; then g_W = L row-major.
// ---------------------------------------------------------------------------
__global__ void __launch_bounds__(1024) setup2_kernel()
{
    const int b = blockIdx.x, tid = threadIdx.x;
    const int r = tid & 255, s = tid >> 8;
    float* M = g_M + (size_t)b * NV * NV;
    extern __shared__ float Lc[];                // 192*256
    __shared__ float psum[1024];
    __shared__ float st[32][33];
    __shared__ float sdiag;

    for (int j = 0; j < NV; j++) {
        float acc = 0.0f;
        const int kc = j < 192 ? j : 192;
#pragma unroll 4
        for (int k = s; k < kc; k += 4)
            acc -= Lc[k*NV + r] * Lc[k*NV + j];
        for (int k = 192 + s; k < j; k += 4)
            acc -= M[(size_t)k*NV + r] * M[(size_t)k*NV + j];
        psum[tid] = acc;
        __syncthreads();
        float a = 0.0f;
        if (s == 0) {
            a = M[(size_t)j*NV + r] + psum[r] + psum[r+256] + psum[r+512] + psum[r+768];
            if (r == j) sdiag = a;
        }
        __syncthreads();
        if (s == 0 && r >= j) {
            float val = a * rsqrtf(sdiag);
            M[(size_t)j*NV + r] = val;
            if (j < 192) Lc[j*NV + r] = val;
        }
        __syncthreads();
    }

    float* W = g_W + (size_t)b * NV * NV;
    const int ty = tid >> 5, tx = tid & 31;
    for (int k0 = 0; k0 < NV; k0 += 32) {
        for (int i0 = 0; i0 < NV; i0 += 32) {
            st[ty][tx] = (k0 + ty < 192) ? Lc[(k0+ty)*NV + i0 + tx]
                                         : M[(size_t)(k0+ty)*NV + i0 + tx];
            __syncthreads();
            W[(size_t)(i0+ty)*NV + k0 + tx] = st[tx][ty];
            __syncthreads();
        }
    }
}

// ---------------------------------------------------------------------------
// minv: block (g, b) computes 128 columns of M^{-1}. 1024 threads, 1 wave.
// ---------------------------------------------------------------------------
__global__ void __launch_bounds__(1024) minv_kernel()
{
    const int g = blockIdx.x, b = blockIdx.y, tid = threadIdx.x;
    const int c0 = g * 128;
    extern __shared__ float sm[];
    float* Yf    = sm;            // 32768
    float* Lp    = sm + 32768;    // 16384
    float* rdiag = sm + 49152;    // 256
    const float* M  = g_M + (size_t)b * NV * NV;
    const float* Wt = g_W + (size_t)b * NV * NV;

    if (tid < NV) rdiag[tid] = 1.0f / M[(size_t)tid*NV + tid];
    for (int idx = tid; idx < 32768; idx += 1024) Yf[idx] = 0.0f;
    __syncthreads();
    if (tid < 128) Yf[(c0 + tid)*128 + tid] = 1.0f;
    __syncthreads();

    const int qd = tid >> 6, c2 = tid & 63;
    float2* Y2 = (float2*)Yf;

    for (int i = c0; i < NV; i++) {
        if ((i & 63) == 0) {
            for (int idx = tid; idx < 16384; idx += 1024)
                Lp[idx] = M[(size_t)(i + (idx >> 8)) * NV + (idx & 255)];
            __syncthreads();
        }
        if (tid < 128) Yf[i*128 + tid] *= rdiag[i];
        __syncthreads();
        float2 yv = Y2[i*64 + c2];
        const float* lcol = Lp + (i & 63) * NV;
        for (int i2 = i + 1 + ((qd - (i + 1)) & 15); i2 < NV; i2 += 16) {
            float lv = lcol[i2];
            float2 t = Y2[i2*64 + c2];
            t.x = fmaf(-lv, yv.x, t.x);
            t.y = fmaf(-lv, yv.y, t.y);
            Y2[i2*64 + c2] = t;
        }
        __syncthreads();
    }

    for (int i = NV - 1; i >= 0; i--) {
        if ((i & 63) == 63) {
            const int p = i - 63;
            for (int idx = tid; idx < 16384; idx += 1024)
                Lp[idx] = Wt[(size_t)(p + (idx >> 8)) * NV + (idx & 255)];
            __syncthreads();
        }
        if (tid < 128) Yf[i*128 + tid] *= rdiag[i];
        __syncthreads();
        float2 xv = Y2[i*64 + c2];
        const float* lrow = Lp + (i & 63) * NV;
        for (int i2 = qd; i2 < i; i2 += 16) {
            float lv = lrow[i2];
            float2 t = Y2[i2*64 + c2];
            t.x = fmaf(-lv, xv.x, t.x);
            t.y = fmaf(-lv, xv.y, t.y);
            Y2[i2*64 + c2] = t;
        }
        __syncthreads();
    }

    float* Mi = g_Minv + (size_t)b * NV * NV;
    for (int idx = tid; idx < 32768; idx += 1024)
        Mi[(size_t)(idx >> 7) * NV + c0 + (idx & 127)] = Yf[idx];
}

__global__ void noop_kernel() {}

// ---------------------------------------------------------------------------
// admm: 2-CTA cluster per batch, 1024 threads/CTA, 100 iterations per launch.
// ---------------------------------------------------------------------------
__global__ void __launch_bounds__(1024, 1) __cluster_dims__(2, 1, 1)
admm_kernel(const float* __restrict__ A, const float* __restrict__ q,
            const float* __restrict__ l, const float* __restrict__ u,
            float* __restrict__ out, int phase)
{
    const int b = blockIdx.x >> 1, r = blockIdx.x & 1;
    const int tid = threadIdx.x;
    extern __shared__ float sh[];
    float4* As4   = (float4*)sh;          // 192 rows x 64 float4, swizzled
    float*  red   = sh + 49152;           // 4096
    float*  w_s   = sh + 53248;           // 256 (own m-half)
    float*  rhs_s = sh + 53504;           // 256
    float*  xt_s  = sh + 53760;           // 256 (full, assembled)
    float*  xs    = sh + 54016;           // 256
    float*  qs    = sh + 54272;           // 256
    float*  prb   = sh + 54528;           // 256 (peer's GEMV1 partial lands here)

    const float SIGMA = 1e-6f, RHO = 0.1f, ALPHA = 1.6f;
    const float4* A4g = (const float4*)(A + (size_t)b * MCON * NV);
    const float4* Mi4 = (const float4*)(g_Minv + (size_t)b * NV * NV);
    const float4* rhs4 = (const float4*)rhs_s;
    const float4* xt4  = (const float4*)xt_s;
    float4* red4 = (float4*)red;

    // Cache own 192 A rows, XOR-swizzled in float4 units.
    for (int i4 = tid; i4 < 192*64; i4 += 1024) {
        const int ml = i4 >> 6, k4 = i4 & 63;
        As4[ml*64 + (k4 ^ (ml & 7))] = A4g[(r*256 + ml)*64 + k4];
    }

    const int mown = tid >> 2, qu = tid & 3;
    const bool owner = (qu == 0);
    const int mg = r*256 + mown;
    float z_r = 0.f, y_r = 0.f, l_r = 0.f, u_r = 0.f;
    float* st = g_state + (size_t)b * 1280;
    if (owner) {
        l_r = l[b*MCON + mg]; u_r = u[b*MCON + mg];
        if (phase) { z_r = st[256 + mg]; y_r = st[768 + mg]; }
        w_s[mown] = fmaf(RHO, z_r, -y_r);
    }
    if (tid < NV) {
        qs[tid] = q[b*NV + tid];
        xs[tid] = phase ? st[tid] : 0.0f;
    }

    // DSMEM target addresses in peer CTA (same smem offsets)
    const uint32_t peer = (uint32_t)(r ^ 1);
    uint32_t ra_prb = 0, ra_xt = 0;
    if (tid < 256) ra_prb = mapa_u32((uint32_t)__cvta_generic_to_shared(prb + tid), peer);
    if (tid < 128) ra_xt  = mapa_u32((uint32_t)__cvta_generic_to_shared(xt_s + r*128 + tid), peer);

    const int ms = tid >> 6, jg = tid & 63;      // GEMV1: 16 m-groups x 64 f4-cols
    const int jx = jg ^ (ms & 7);
    const int ks2 = tid & 7, jo = tid >> 3;      // GEMV2: 8 k-groups x 128 outputs
    const int jglob = r*128 + jo;
    __syncthreads();

    for (int it = 0; it < 100; it++) {
        // ---- GEMV1: partial A^T w over own m-half ----
        float4 acc = {0.f, 0.f, 0.f, 0.f};
        float4 t0 = __ldcg(A4g + (r*256 + ms + 192)*64 + jg);
        float4 t1 = __ldcg(A4g + (r*256 + ms + 208)*64 + jg);
        float4 t2 = __ldcg(A4g + (r*256 + ms + 224)*64 + jg);
        float4 t3 = __ldcg(A4g + (r*256 + ms + 240)*64 + jg);
#pragma unroll
        for (int t = 0; t < 12; t++)
            fma4(acc, As4[(ms + 16*t)*64 + jx], w_s[ms + 16*t]);
        fma4(acc, t0, w_s[ms + 192]);
        fma4(acc, t1, w_s[ms + 208]);
        fma4(acc, t2, w_s[ms + 224]);
        fma4(acc, t3, w_s[ms + 240]);
        red4[ms*64 + jg] = acc;
        __syncthreads();                                   // S1
        float ownp = 0.0f;
        if (tid < 256) {
#pragma unroll
            for (int s = 0; s < 16; s++) ownp += red[s*256 + tid];
            st_cluster_f32(ra_prb, ownp);
        }
        CLUSTER_ARRIVE();
        CLUSTER_WAIT();
        if (tid < 256)
            rhs_s[tid] = fmaf(SIGMA, xs[tid], -qs[tid]) + ownp + prb[tid];
        __syncthreads();                                   // S2

        // ---- GEMV2: x~ for own 128 outputs (Minv rows from L2) ----
        float4 a2 = {0.f, 0.f, 0.f, 0.f};
        const float4* Mrow = Mi4 + jglob*64;
#pragma unroll
        for (int t = 0; t < 8; t++)
            dot4(a2, __ldcg(Mrow + ks2 + 8*t), rhs4[ks2 + 8*t]);
        red[jo*8 + ks2] = (a2.x + a2.y) + (a2.z + a2.w);
        __syncthreads();                                   // S3
        if (tid < 128) {
            float v = 0.f;
#pragma unroll
            for (int s = 0; s < 8; s++) v += red[tid*8 + s];
            xt_s[r*128 + tid] = v;
            st_cluster_f32(ra_xt, v);
        }
        CLUSTER_ARRIVE();
        CLUSTER_WAIT();
        if (tid < 256)
            xs[tid] = fmaf(ALPHA, xt_s[tid], (1.0f - ALPHA) * xs[tid]);

        // ---- GEMV3: z~ for own m rows (A rows from SMEM / L2 tail) ----
        float4 a3 = {0.f, 0.f, 0.f, 0.f};
        if (mown < 192) {
            const float4* Arow = As4 + mown*64;
            const int sw = mown & 7;
#pragma unroll
            for (int t = 0; t < 16; t++) {
                const int k4 = qu*16 + ((t + 2*qu) & 15);
                dot4(a3, Arow[k4 ^ sw], xt4[k4]);
            }
        } else {
            const float4* Arow = A4g + (r*256 + mown)*64;
#pragma unroll
            for (int t = 0; t < 16; t++) {
                const int k4 = qu*16 + t;
                dot4(a3, __ldcg(Arow + k4), xt4[k4]);
            }
        }
        float s3 = (a3.x + a3.y) + (a3.z + a3.w);
        s3 += __shfl_xor_sync(0xffffffffu, s3, 1);
        s3 += __shfl_xor_sync(0xffffffffu, s3, 2);
        if (owner) {
            float zr = fmaf(ALPHA, s3, (1.0f - ALPHA) * z_r);
            float zc = fminf(fmaxf(fmaf(y_r, 10.0f, zr), l_r), u_r);  // 1/RHO=10
            y_r = fmaf(RHO, zr - zc, y_r);
            z_r = zc;
            w_s[mown] = fmaf(RHO, z_r, -y_r);
        }
        __syncthreads();                                   // S4
    }

    if (phase == 0) {
        if (owner) { st[256 + mg] = z_r; st[768 + mg] = y_r; }
        if (r == 0 && tid < NV) st[tid] = xs[tid];
    } else {
        if (r == 0 && tid < NV) out[b*NV + tid] = xs[tid];
    }
}

// ---------------------------------------------------------------------------
extern "C" void kernel_launch(void* const* d_in, const int* in_sizes, int n_in,
                              void* d_out, int out_size)
{
    const float* P = (const float*)d_in[0];
    const float* q = (const float*)d_in[1];
    const float* A = (const float*)d_in[2];
    const float* l = (const float*)d_in[3];
    const float* u = (const float*)d_in[4];
    float* out = (float*)d_out;

    const int CHOL_SMEM = 192 * 256 * 4;                 // 196608
    const int MINV_SMEM = (32768 + 16384 + 256) * 4;     // 197632
    const int ADMM_SMEM = 54784 * 4;                     // 219136
    cudaFuncSetAttribute(setup2_kernel, cudaFuncAttributeMaxDynamicSharedMemorySize, CHOL_SMEM);
    cudaFuncSetAttribute(minv_kernel,   cudaFuncAttributeMaxDynamicSharedMemorySize, MINV_SMEM);
    cudaFuncSetAttribute(admm_kernel,   cudaFuncAttributeMaxDynamicSharedMemorySize, ADMM_SMEM);

    setup1_kernel<<<dim3(10, NBAT), 256>>>(A, P);
    setup2_kernel<<<NBAT, 1024, CHOL_SMEM>>>();
    minv_kernel<<<dim3(2, NBAT), 1024, MINV_SMEM>>>();
    admm_kernel<<<2 * NBAT, 1024, ADMM_SMEM>>>(A, q, l, u, out, 0);
    noop_kernel<<<1, 32>>>();
    admm_kernel<<<2 * NBAT, 1024, ADMM_SMEM>>>(A, q, l, u, out, 1);
}